// round 5
// baseline (speedup 1.0000x reference)
#include <cuda_runtime.h>
#include <cuda_bf16.h>

#define N_NODES_MAX 50000
#define HF 64

// Scratch tables: A[n] = h[n] @ W1[0:64,:] + b1, B[n] = h[n] @ W1[64:128,:]
__device__ float gA[N_NODES_MAX * HF];
__device__ float gB[N_NODES_MAX * HF];

// ---------------------------------------------------------------------------
// Kernel 1: per-node precompute (64 nodes x 128 cols tile, 256 thr, 4x8/thread)
// Plain FFMA version (proven fastest; f32x2 packed path regressed).
// ---------------------------------------------------------------------------
__global__ __launch_bounds__(256) void node_precompute(
    const float* __restrict__ h,
    const float* __restrict__ W1,
    const float* __restrict__ b1,
    int n_nodes)
{
    __shared__ float sh[64 * 64];    // sh[m][k]
    __shared__ float sW[64 * 128];   // sW[k][jj]

    const int t = threadIdx.x;
    const int node0 = blockIdx.x * 64;

    for (int i = t; i < 64 * 128; i += 256) {
        int k  = i >> 7;
        int jj = i & 127;
        sW[i] = W1[(k + (jj & 64)) * 64 + (jj & 63)];
    }
    for (int i = t; i < 64 * 64; i += 256) {
        int m = i >> 6;
        int k = i & 63;
        int n = node0 + m;
        sh[i] = (n < n_nodes) ? h[n * 64 + k] : 0.f;
    }
    __syncthreads();

    const int tx = t & 15;   // jj0 = tx*8
    const int ty = t >> 4;   // m0  = ty*4

    float acc[4][8];
#pragma unroll
    for (int m = 0; m < 4; m++)
#pragma unroll
        for (int j = 0; j < 8; j++) acc[m][j] = 0.f;

#pragma unroll 8
    for (int k = 0; k < 64; k++) {
        float a[4];
#pragma unroll
        for (int m = 0; m < 4; m++) a[m] = sh[(ty * 4 + m) * 64 + k];
        const float4 w0 = *reinterpret_cast<const float4*>(&sW[k * 128 + tx * 8]);
        const float4 w1 = *reinterpret_cast<const float4*>(&sW[k * 128 + tx * 8 + 4]);
#pragma unroll
        for (int m = 0; m < 4; m++) {
            acc[m][0] = fmaf(a[m], w0.x, acc[m][0]);
            acc[m][1] = fmaf(a[m], w0.y, acc[m][1]);
            acc[m][2] = fmaf(a[m], w0.z, acc[m][2]);
            acc[m][3] = fmaf(a[m], w0.w, acc[m][3]);
            acc[m][4] = fmaf(a[m], w1.x, acc[m][4]);
            acc[m][5] = fmaf(a[m], w1.y, acc[m][5]);
            acc[m][6] = fmaf(a[m], w1.z, acc[m][6]);
            acc[m][7] = fmaf(a[m], w1.w, acc[m][7]);
        }
    }

    const int jj0 = tx * 8;
    const bool isA = (jj0 < 64);
    float bb[8];
#pragma unroll
    for (int j = 0; j < 8; j++) bb[j] = isA ? __ldg(&b1[jj0 + j]) : 0.f;

#pragma unroll
    for (int m = 0; m < 4; m++) {
        int n = node0 + ty * 4 + m;
        if (n >= n_nodes) break;
        float* dst = isA ? (&gA[n * 64 + jj0]) : (&gB[n * 64 + (jj0 - 64)]);
        float4 o0 = make_float4(acc[m][0] + bb[0], acc[m][1] + bb[1],
                                acc[m][2] + bb[2], acc[m][3] + bb[3]);
        float4 o1 = make_float4(acc[m][4] + bb[4], acc[m][5] + bb[5],
                                acc[m][6] + bb[6], acc[m][7] + bb[7]);
        *reinterpret_cast<float4*>(dst)     = o0;
        *reinterpret_cast<float4*>(dst + 4) = o1;
    }
}

// ---------------------------------------------------------------------------
// Kernel 2: per-edge scoring.
// 16 lanes per edge-group, 2 edges per group, 4 edges per warp.
// Each lane: one float4 per table row (16 lanes cover the full 256B row),
// 4 independent LDG.128 per thread, width-16 shuffle reduction,
// coalesced 4-edge epilogue (lanes 0-3 write consecutive outputs).
// ---------------------------------------------------------------------------
__global__ __launch_bounds__(256) void edge_score(
    const int* __restrict__ src,
    const int* __restrict__ dst,
    const float* __restrict__ W2,
    const float* __restrict__ b2,
    float* __restrict__ out,
    int n_edges, int n_nodes)
{
    const int tid  = blockIdx.x * blockDim.x + threadIdx.x;
    const int lane = threadIdx.x & 31;
    const int grp  = lane >> 4;            // 0..1 within warp
    const int gl   = lane & 15;            // lane within 16-lane group
    const int warp = tid >> 5;
    const int we0  = warp * 4;             // first edge of this warp
    const int gp   = warp * 2 + grp;       // edge-pair id for this group
    const int e0   = gp * 2;               // first edge of this group
    if (e0 >= n_edges) return;
    const bool has1 = (e0 + 1) < n_edges;

    int s0, d0, s1, d1;
    if (has1) {
        const int2 ss = __ldg(reinterpret_cast<const int2*>(src) + gp);
        const int2 dd = __ldg(reinterpret_cast<const int2*>(dst) + gp);
        s0 = ss.x; s1 = ss.y; d0 = dd.x; d1 = dd.y;
    } else {
        s0 = __ldg(&src[e0]); d0 = __ldg(&dst[e0]); s1 = s0; d1 = d0;
    }
    s0 = min(max(s0, 0), n_nodes - 1);
    d0 = min(max(d0, 0), n_nodes - 1);
    s1 = min(max(s1, 0), n_nodes - 1);
    d1 = min(max(d1, 0), n_nodes - 1);

    // Lane gl covers hidden features gl*4 .. gl*4+3
    const float4 w = __ldg(reinterpret_cast<const float4*>(W2) + gl);

    const float4 a0 = __ldg(reinterpret_cast<const float4*>(gA + (size_t)s0 * HF) + gl);
    const float4 b0 = __ldg(reinterpret_cast<const float4*>(gB + (size_t)d0 * HF) + gl);
    const float4 a1 = __ldg(reinterpret_cast<const float4*>(gA + (size_t)s1 * HF) + gl);
    const float4 b1 = __ldg(reinterpret_cast<const float4*>(gB + (size_t)d1 * HF) + gl);

    float p;
    p =       fmaxf(a0.x + b0.x, 0.f) * w.x;
    p = fmaf( fmaxf(a0.y + b0.y, 0.f), w.y, p);
    p = fmaf( fmaxf(a0.z + b0.z, 0.f), w.z, p);
    p = fmaf( fmaxf(a0.w + b0.w, 0.f), w.w, p);

    float q;
    q =       fmaxf(a1.x + b1.x, 0.f) * w.x;
    q = fmaf( fmaxf(a1.y + b1.y, 0.f), w.y, q);
    q = fmaf( fmaxf(a1.z + b1.z, 0.f), w.z, q);
    q = fmaf( fmaxf(a1.w + b1.w, 0.f), w.w, q);

    // width-16 reductions (interleaved)
    p += __shfl_xor_sync(0xFFFFFFFFu, p, 8);
    q += __shfl_xor_sync(0xFFFFFFFFu, q, 8);
    p += __shfl_xor_sync(0xFFFFFFFFu, p, 4);
    q += __shfl_xor_sync(0xFFFFFFFFu, q, 4);
    p += __shfl_xor_sync(0xFFFFFFFFu, p, 2);
    q += __shfl_xor_sync(0xFFFFFFFFu, q, 2);
    p += __shfl_xor_sync(0xFFFFFFFFu, p, 1);
    q += __shfl_xor_sync(0xFFFFFFFFu, q, 1);
    // p (edge e0) and q (edge e0+1) now valid at gl==0 (lanes 0 and 16)

    // Gather the warp's 4 scores to lanes 0-3 for coalesced stores:
    // lane i<4 handles edge we0+i, source lane ((i>>1)&1)*16, parity i&1.
    const int srcl = ((lane >> 1) & 1) * 16;
    const float pv = __shfl_sync(0xFFFFFFFFu, p, srcl);
    const float qv = __shfl_sync(0xFFFFFFFFu, q, srcl);

    if (lane < 4) {
        const int e = we0 + lane;
        if (e < n_edges) {
            const float sc = ((lane & 1) ? qv : pv) + __ldg(&b2[0]);
            out[e] = sc;
            // label = round(sigmoid(score)); rintf = round-half-even (jnp.round)
            out[n_edges + e] = rintf(1.f / (1.f + expf(-sc)));
        }
    }
}

// ---------------------------------------------------------------------------
// Launch: inputs in order h, src, dst, W1, b1, W2, b2
// ---------------------------------------------------------------------------
extern "C" void kernel_launch(void* const* d_in, const int* in_sizes, int n_in,
                              void* d_out, int out_size)
{
    const float* h   = (const float*)d_in[0];
    const int*   src = (const int*)d_in[1];
    const int*   dst = (const int*)d_in[2];
    const float* W1  = (const float*)d_in[3];
    const float* b1  = (const float*)d_in[4];
    const float* W2  = (const float*)d_in[5];
    const float* b2  = (const float*)d_in[6];
    float* out = (float*)d_out;

    const int n_nodes = in_sizes[0] / HF;
    const int n_edges = in_sizes[1];

    const int blocks1 = (n_nodes + 63) / 64;
    node_precompute<<<blocks1, 256>>>(h, W1, b1, n_nodes);

    // 4 edges per warp -> 8 threads per edge
    const long long total_threads = (long long)((n_edges + 3) / 4) * 32;
    const int blocks2 = (int)((total_threads + 255) / 256);
    edge_score<<<blocks2, 256>>>(src, dst, W2, b2, out, n_edges, n_nodes);
}

// round 6
// speedup vs baseline: 1.1437x; 1.1437x over previous
#include <cuda_runtime.h>
#include <cuda_bf16.h>

#define N_NODES_MAX 50000
#define HF 64

// Scratch tables: A[n] = h[n] @ W1[0:64,:] + b1, B[n] = h[n] @ W1[64:128,:]
__device__ float gA[N_NODES_MAX * HF];
__device__ float gB[N_NODES_MAX * HF];

// ---------------------------------------------------------------------------
// Kernel 1: per-node precompute (64 nodes x 128 cols tile, 256 thr, 4x8/thread)
// Plain FFMA (proven fastest; packed f32x2 regressed in R4).
// ---------------------------------------------------------------------------
__global__ __launch_bounds__(256) void node_precompute(
    const float* __restrict__ h,
    const float* __restrict__ W1,
    const float* __restrict__ b1,
    int n_nodes)
{
    __shared__ float sh[64 * 64];    // sh[m][k]
    __shared__ float sW[64 * 128];   // sW[k][jj]

    const int t = threadIdx.x;
    const int node0 = blockIdx.x * 64;

    for (int i = t; i < 64 * 128; i += 256) {
        int k  = i >> 7;
        int jj = i & 127;
        sW[i] = W1[(k + (jj & 64)) * 64 + (jj & 63)];
    }
    for (int i = t; i < 64 * 64; i += 256) {
        int m = i >> 6;
        int k = i & 63;
        int n = node0 + m;
        sh[i] = (n < n_nodes) ? h[n * 64 + k] : 0.f;
    }
    __syncthreads();

    const int tx = t & 15;   // jj0 = tx*8
    const int ty = t >> 4;   // m0  = ty*4

    float acc[4][8];
#pragma unroll
    for (int m = 0; m < 4; m++)
#pragma unroll
        for (int j = 0; j < 8; j++) acc[m][j] = 0.f;

#pragma unroll 8
    for (int k = 0; k < 64; k++) {
        float a[4];
#pragma unroll
        for (int m = 0; m < 4; m++) a[m] = sh[(ty * 4 + m) * 64 + k];
        const float4 w0 = *reinterpret_cast<const float4*>(&sW[k * 128 + tx * 8]);
        const float4 w1 = *reinterpret_cast<const float4*>(&sW[k * 128 + tx * 8 + 4]);
#pragma unroll
        for (int m = 0; m < 4; m++) {
            acc[m][0] = fmaf(a[m], w0.x, acc[m][0]);
            acc[m][1] = fmaf(a[m], w0.y, acc[m][1]);
            acc[m][2] = fmaf(a[m], w0.z, acc[m][2]);
            acc[m][3] = fmaf(a[m], w0.w, acc[m][3]);
            acc[m][4] = fmaf(a[m], w1.x, acc[m][4]);
            acc[m][5] = fmaf(a[m], w1.y, acc[m][5]);
            acc[m][6] = fmaf(a[m], w1.z, acc[m][6]);
            acc[m][7] = fmaf(a[m], w1.w, acc[m][7]);
        }
    }

    const int jj0 = tx * 8;
    const bool isA = (jj0 < 64);
    float bb[8];
#pragma unroll
    for (int j = 0; j < 8; j++) bb[j] = isA ? __ldg(&b1[jj0 + j]) : 0.f;

#pragma unroll
    for (int m = 0; m < 4; m++) {
        int n = node0 + ty * 4 + m;
        if (n >= n_nodes) break;
        float* dst = isA ? (&gA[n * 64 + jj0]) : (&gB[n * 64 + (jj0 - 64)]);
        float4 o0 = make_float4(acc[m][0] + bb[0], acc[m][1] + bb[1],
                                acc[m][2] + bb[2], acc[m][3] + bb[3]);
        float4 o1 = make_float4(acc[m][4] + bb[4], acc[m][5] + bb[5],
                                acc[m][6] + bb[6], acc[m][7] + bb[7]);
        *reinterpret_cast<float4*>(dst)     = o0;
        *reinterpret_cast<float4*>(dst + 4) = o1;
    }
}

// ---------------------------------------------------------------------------
// Kernel 2: per-edge scoring (R4 shape, proven fastest: 47.2us).
// 8 lanes per group, TWO edges per group, 8 edges per warp.
// 8 independent LDG.128 per thread; 6 warp-SHFL per 8 edges.
// Clamps removed (indices proven valid in-range int32).
// ---------------------------------------------------------------------------
__global__ __launch_bounds__(256) void edge_score(
    const int* __restrict__ src,
    const int* __restrict__ dst,
    const float* __restrict__ W2,
    const float* __restrict__ b2,
    float* __restrict__ out,
    int n_edges)
{
    const int tid = blockIdx.x * blockDim.x + threadIdx.x;
    const int gl  = threadIdx.x & 7;
    const int g   = tid >> 3;          // group id, handles edges 2g, 2g+1
    const int e0  = g * 2;
    if (e0 >= n_edges) return;
    const bool has1 = (e0 + 1) < n_edges;

    int s0, d0, s1, d1;
    if (has1) {
        const int2 ss = __ldg(reinterpret_cast<const int2*>(src) + g);
        const int2 dd = __ldg(reinterpret_cast<const int2*>(dst) + g);
        s0 = ss.x; s1 = ss.y; d0 = dd.x; d1 = dd.y;
    } else {
        s0 = __ldg(&src[e0]); d0 = __ldg(&dst[e0]); s1 = s0; d1 = d0;
    }

    const float4 w0 = __ldg(reinterpret_cast<const float4*>(W2) + gl);
    const float4 w1 = __ldg(reinterpret_cast<const float4*>(W2) + gl + 8);

    const float4* pa0 = reinterpret_cast<const float4*>(gA + (size_t)s0 * HF) + gl;
    const float4* pb0 = reinterpret_cast<const float4*>(gB + (size_t)d0 * HF) + gl;
    const float4* pa1 = reinterpret_cast<const float4*>(gA + (size_t)s1 * HF) + gl;
    const float4* pb1 = reinterpret_cast<const float4*>(gB + (size_t)d1 * HF) + gl;

    const float4 A0 = __ldg(pa0);
    const float4 A1 = __ldg(pa0 + 8);
    const float4 B0 = __ldg(pb0);
    const float4 B1 = __ldg(pb0 + 8);
    const float4 C0 = __ldg(pa1);
    const float4 C1 = __ldg(pa1 + 8);
    const float4 D0 = __ldg(pb1);
    const float4 D1 = __ldg(pb1 + 8);

    float p;
    p =       fmaxf(A0.x + B0.x, 0.f) * w0.x;
    p = fmaf( fmaxf(A0.y + B0.y, 0.f), w0.y, p);
    p = fmaf( fmaxf(A0.z + B0.z, 0.f), w0.z, p);
    p = fmaf( fmaxf(A0.w + B0.w, 0.f), w0.w, p);
    p = fmaf( fmaxf(A1.x + B1.x, 0.f), w1.x, p);
    p = fmaf( fmaxf(A1.y + B1.y, 0.f), w1.y, p);
    p = fmaf( fmaxf(A1.z + B1.z, 0.f), w1.z, p);
    p = fmaf( fmaxf(A1.w + B1.w, 0.f), w1.w, p);

    float q;
    q =       fmaxf(C0.x + D0.x, 0.f) * w0.x;
    q = fmaf( fmaxf(C0.y + D0.y, 0.f), w0.y, q);
    q = fmaf( fmaxf(C0.z + D0.z, 0.f), w0.z, q);
    q = fmaf( fmaxf(C0.w + D0.w, 0.f), w0.w, q);
    q = fmaf( fmaxf(C1.x + D1.x, 0.f), w1.x, q);
    q = fmaf( fmaxf(C1.y + D1.y, 0.f), w1.y, q);
    q = fmaf( fmaxf(C1.z + D1.z, 0.f), w1.z, q);
    q = fmaf( fmaxf(C1.w + D1.w, 0.f), w1.w, q);

    // width-8 reductions (independent -> interleaved)
    p += __shfl_xor_sync(0xFFFFFFFFu, p, 4);
    q += __shfl_xor_sync(0xFFFFFFFFu, q, 4);
    p += __shfl_xor_sync(0xFFFFFFFFu, p, 2);
    q += __shfl_xor_sync(0xFFFFFFFFu, q, 2);
    p += __shfl_xor_sync(0xFFFFFFFFu, p, 1);
    q += __shfl_xor_sync(0xFFFFFFFFu, q, 1);

    if (gl == 0) {
        const float bias = __ldg(&b2[0]);
        const float sc0 = p + bias;
        out[e0] = sc0;
        // label = round(sigmoid(score)); exact expf/rintf required
        // (a single label flip exceeds the 1e-3 rel-err budget)
        out[n_edges + e0] = rintf(1.f / (1.f + expf(-sc0)));
        if (has1) {
            const float sc1 = q + bias;
            out[e0 + 1] = sc1;
            out[n_edges + e0 + 1] = rintf(1.f / (1.f + expf(-sc1)));
        }
    }
}

// ---------------------------------------------------------------------------
// Launch: inputs in order h, src, dst, W1, b1, W2, b2
// ---------------------------------------------------------------------------
extern "C" void kernel_launch(void* const* d_in, const int* in_sizes, int n_in,
                              void* d_out, int out_size)
{
    const float* h   = (const float*)d_in[0];
    const int*   src = (const int*)d_in[1];
    const int*   dst = (const int*)d_in[2];
    const float* W1  = (const float*)d_in[3];
    const float* b1  = (const float*)d_in[4];
    const float* W2  = (const float*)d_in[5];
    const float* b2  = (const float*)d_in[6];
    float* out = (float*)d_out;

    const int n_nodes = in_sizes[0] / HF;
    const int n_edges = in_sizes[1];

    const int blocks1 = (n_nodes + 63) / 64;
    node_precompute<<<blocks1, 256>>>(h, W1, b1, n_nodes);

    const long long groups = (n_edges + 1) / 2;          // 2 edges per 8-lane group
    const long long total_threads = groups * 8;
    const int blocks2 = (int)((total_threads + 255) / 256);
    edge_score<<<blocks2, 256>>>(src, dst, W2, b2, out, n_edges);
}